// round 10
// baseline (speedup 1.0000x reference)
#include <cuda_runtime.h>

#define NB 4
#define NN 900
#define ND 256
#define NV 16
#define NH 8
#define NN2 (NN * NN)

// scratch: x = 1 - imap/Z, laid out (B,N,N) contiguous
__device__ float g_x[NB * NN2];

__device__ __forceinline__ float fast_ex2(float x) {
    float r; asm("ex2.approx.ftz.f32 %0, %1;" : "=f"(r) : "f"(x)); return r;
}
__device__ __forceinline__ float fast_sin(float x) {
    float r; asm("sin.approx.ftz.f32 %0, %1;" : "=f"(r) : "f"(x)); return r;
}
__device__ __forceinline__ float fast_cos(float x) {
    float r; asm("cos.approx.ftz.f32 %0, %1;" : "=f"(r) : "f"(x)); return r;
}
__device__ __forceinline__ unsigned long long pack2(float a, float b) {
    unsigned long long r;
    asm("mov.b64 %0, {%1, %2};" : "=l"(r)
        : "r"(__float_as_uint(a)), "r"(__float_as_uint(b)));
    return r;
}
__device__ __forceinline__ float2 unpack2(unsigned long long v) {
    unsigned int lo, hi;
    asm("mov.b64 {%0, %1}, %2;" : "=r"(lo), "=r"(hi) : "l"(v));
    return make_float2(__uint_as_float(lo), __uint_as_float(hi));
}
__device__ __forceinline__ unsigned long long fma2(unsigned long long a,
                                                   unsigned long long b,
                                                   unsigned long long c) {
    unsigned long long d;
    asm("fma.rn.f32x2 %0, %1, %2, %3;" : "=l"(d) : "l"(a), "l"(b), "l"(c));
    return d;
}

// ---------------------------------------------------------------------------
// Kernel A: TWO rows (n0, n0+1) per block; 4 vote-groups of 64 threads.
// Inner loop: votes packed in f32x2 pairs -> 3 FFMA2 per (row, vote-pair).
// m-loop unrolled x2 so the scheduler can interleave two iterations' chains.
// ---------------------------------------------------------------------------
__global__ __launch_bounds__(256, 4)
void hough_row2_kernel(const float* __restrict__ q,     // (B,N,D)
                       const float* __restrict__ cur,   // (B,N,4)
                       const float* __restrict__ vw,    // (32,D)
                       const float* __restrict__ vb)    // (32)
{
    const int pair = blockIdx.x;          // 0 .. NB*NN/2-1
    const int b    = pair / (NN / 2);
    const int n0   = (pair % (NN / 2)) * 2;
    const int bn0  = b * NN + n0;
    const int tid  = threadIdx.x;
    const int lane = tid & 31;
    const int w    = tid >> 5;
    const int g    = tid >> 6;            // vote group 0..3
    const int tg   = tid & 63;

    __shared__ float4 sq4[2][ND / 4];
    __shared__ float2 sC[NN];
    __shared__ float  sI[2][4][NN];
    __shared__ float4 sCoef[2][NV];       // (Ax, Ay, Ni, C0)
    __shared__ float  sVotes[2][2 * NV];
    __shared__ float  sRed[2][8];
    __shared__ float  sInvZ[2];

    if (tid < 128) {
        int r = tid >> 6, i = tid & 63;
        sq4[r][i] = *reinterpret_cast<const float4*>(q + (bn0 + r) * ND + i * 4);
    }
    for (int j = tid; j < NN; j += 256) {
        float4 c4 = *reinterpret_cast<const float4*>(cur + (b * NN + j) * 4);
        sC[j] = make_float2(c4.x, c4.y);
    }
    __syncthreads();

    // votes for BOTH rows: weight vectors loaded once, used with both q rows
    {
        const int k0 = w * 4;
        const float4* w0 = reinterpret_cast<const float4*>(vw + (k0 + 0) * ND);
        const float4* w1 = reinterpret_cast<const float4*>(vw + (k0 + 1) * ND);
        const float4* w2 = reinterpret_cast<const float4*>(vw + (k0 + 2) * ND);
        const float4* w3 = reinterpret_cast<const float4*>(vw + (k0 + 3) * ND);
        float a0 = 0.f, a1 = 0.f, a2 = 0.f, a3 = 0.f;
        float b0 = 0.f, b1 = 0.f, b2 = 0.f, b3 = 0.f;
        #pragma unroll
        for (int i = 0; i < 2; i++) {
            int d = lane + 32 * i;
            float4 qa = sq4[0][d];
            float4 qb = sq4[1][d];
            float4 v0 = __ldg(w0 + d);
            float4 v1 = __ldg(w1 + d);
            float4 v2 = __ldg(w2 + d);
            float4 v3 = __ldg(w3 + d);
            a0 = fmaf(qa.x, v0.x, fmaf(qa.y, v0.y, fmaf(qa.z, v0.z, fmaf(qa.w, v0.w, a0))));
            a1 = fmaf(qa.x, v1.x, fmaf(qa.y, v1.y, fmaf(qa.z, v1.z, fmaf(qa.w, v1.w, a1))));
            a2 = fmaf(qa.x, v2.x, fmaf(qa.y, v2.y, fmaf(qa.z, v2.z, fmaf(qa.w, v2.w, a2))));
            a3 = fmaf(qa.x, v3.x, fmaf(qa.y, v3.y, fmaf(qa.z, v3.z, fmaf(qa.w, v3.w, a3))));
            b0 = fmaf(qb.x, v0.x, fmaf(qb.y, v0.y, fmaf(qb.z, v0.z, fmaf(qb.w, v0.w, b0))));
            b1 = fmaf(qb.x, v1.x, fmaf(qb.y, v1.y, fmaf(qb.z, v1.z, fmaf(qb.w, v1.w, b1))));
            b2 = fmaf(qb.x, v2.x, fmaf(qb.y, v2.y, fmaf(qb.z, v2.z, fmaf(qb.w, v2.w, b2))));
            b3 = fmaf(qb.x, v3.x, fmaf(qb.y, v3.y, fmaf(qb.z, v3.z, fmaf(qb.w, v3.w, b3))));
        }
        #pragma unroll
        for (int o = 16; o; o >>= 1) {
            a0 += __shfl_down_sync(0xffffffffu, a0, o);
            a1 += __shfl_down_sync(0xffffffffu, a1, o);
            a2 += __shfl_down_sync(0xffffffffu, a2, o);
            a3 += __shfl_down_sync(0xffffffffu, a3, o);
            b0 += __shfl_down_sync(0xffffffffu, b0, o);
            b1 += __shfl_down_sync(0xffffffffu, b1, o);
            b2 += __shfl_down_sync(0xffffffffu, b2, o);
            b3 += __shfl_down_sync(0xffffffffu, b3, o);
        }
        if (lane == 0) {
            sVotes[0][k0 + 0] = a0 + vb[k0 + 0];
            sVotes[0][k0 + 1] = a1 + vb[k0 + 1];
            sVotes[0][k0 + 2] = a2 + vb[k0 + 2];
            sVotes[0][k0 + 3] = a3 + vb[k0 + 3];
            sVotes[1][k0 + 0] = b0 + vb[k0 + 0];
            sVotes[1][k0 + 1] = b1 + vb[k0 + 1];
            sVotes[1][k0 + 2] = b2 + vb[k0 + 2];
            sVotes[1][k0 + 3] = b3 + vb[k0 + 3];
        }
    }
    __syncthreads();

    if (tid < 2 * NV) {
        int r = tid >> 4, v = tid & 15;
        int n = n0 + r, bn = bn0 + r;
        float cx = cur[bn * 4 + 0];
        float cy = cur[bn * 4 + 1];
        float vx = cx + sVotes[r][2 * v + 0];
        float vy = cy + sVotes[r][2 * v + 1];
        // reference quirk: sigma index is (n*V + v) mod N
        int idx  = (n * NV + v) % NN;
        float c2 = cur[(b * NN + idx) * 4 + 2];
        float c3 = cur[(b * NN + idx) * 4 + 3];
        float s  = c2 + c3;   // 4*sigma
        float ninv = -11.541560327111707f / (s * s);   // -8*log2e / s^2
        float vv   = fmaf(vx, vx, vy * vy);
        sCoef[r][v] = make_float4(-2.f * ninv * vx, -2.f * ninv * vy,
                                  ninv, ninv * vv);
    }
    __syncthreads();

    // registerize this group's 4 votes for both rows as f32x2 vote-pairs
    unsigned long long Axp[2][2], Ayp[2][2], Nip[2][2], C0p[2][2];
    #pragma unroll
    for (int r = 0; r < 2; r++)
        #pragma unroll
        for (int p = 0; p < 2; p++) {
            float4 ca = sCoef[r][g * 4 + 2 * p + 0];
            float4 cb = sCoef[r][g * 4 + 2 * p + 1];
            Axp[r][p] = pack2(ca.x, cb.x);
            Ayp[r][p] = pack2(ca.y, cb.y);
            Nip[r][p] = pack2(ca.z, cb.z);
            C0p[r][p] = pack2(ca.w, cb.w);
        }

    float part0 = 0.f, part1 = 0.f;
    #pragma unroll 2
    for (int m = tg; m < NN; m += 64) {
        float2 c  = sC[m];
        float  cc = fmaf(c.x, c.x, c.y * c.y);
        unsigned long long cxd = pack2(c.x, c.x);
        unsigned long long cyd = pack2(c.y, c.y);
        unsigned long long ccd = pack2(cc, cc);

        unsigned long long e00 = fma2(cxd, Axp[0][0], fma2(cyd, Ayp[0][0], fma2(ccd, Nip[0][0], C0p[0][0])));
        unsigned long long e01 = fma2(cxd, Axp[0][1], fma2(cyd, Ayp[0][1], fma2(ccd, Nip[0][1], C0p[0][1])));
        unsigned long long e10 = fma2(cxd, Axp[1][0], fma2(cyd, Ayp[1][0], fma2(ccd, Nip[1][0], C0p[1][0])));
        unsigned long long e11 = fma2(cxd, Axp[1][1], fma2(cyd, Ayp[1][1], fma2(ccd, Nip[1][1], C0p[1][1])));

        float2 f00 = unpack2(e00);
        float2 f01 = unpack2(e01);
        float2 f10 = unpack2(e10);
        float2 f11 = unpack2(e11);

        float acc0 = (fast_ex2(fminf(f00.x, 0.f)) + fast_ex2(fminf(f00.y, 0.f)))
                   + (fast_ex2(fminf(f01.x, 0.f)) + fast_ex2(fminf(f01.y, 0.f)));
        float acc1 = (fast_ex2(fminf(f10.x, 0.f)) + fast_ex2(fminf(f10.y, 0.f)))
                   + (fast_ex2(fminf(f11.x, 0.f)) + fast_ex2(fminf(f11.y, 0.f)));

        sI[0][g][m] = acc0;
        sI[1][g][m] = acc1;
        part0 += acc0;
        part1 += acc1;
    }
    #pragma unroll
    for (int o = 16; o; o >>= 1) {
        part0 += __shfl_down_sync(0xffffffffu, part0, o);
        part1 += __shfl_down_sync(0xffffffffu, part1, o);
    }
    if (lane == 0) { sRed[0][w] = part0; sRed[1][w] = part1; }
    __syncthreads();
    if (tid < 2) {
        float t = 0.f;
        #pragma unroll
        for (int i = 0; i < 8; i++) t += sRed[tid][i];
        sInvZ[tid] = 1.f / fmaxf(t, 1e-12f);
    }
    __syncthreads();
    const float invZ0 = sInvZ[0];
    const float invZ1 = sInvZ[1];

    float* xr0 = g_x + (size_t)bn0 * NN;
    for (int m = tid; m < NN; m += 256) {
        float s0 = (sI[0][0][m] + sI[0][1][m]) + (sI[0][2][m] + sI[0][3][m]);
        float s1 = (sI[1][0][m] + sI[1][1][m]) + (sI[1][2][m] + sI[1][3][m]);
        xr0[m]      = 1.f - s0 * invZ0;
        xr0[NN + m] = 1.f - s1 * invZ1;
    }
}

// ---------------------------------------------------------------------------
// Kernel B: 4 elements per thread (2 f32x2 pairs), j-outer, acc[8][2] in
// registers, 3 CTAs/SM. Weights pre-duplicated in shared as ulonglong2
// {(ws,ws),(wc,wc)} -> one LDS.128 per (j,h), zero dup-MOVs.
// ---------------------------------------------------------------------------
__global__ __launch_bounds__(256, 3)
void embed_proj_kernel(const float* __restrict__ pw,   // (H,16)
                       const float* __restrict__ pb,   // (H)
                       float* __restrict__ out)        // (B,H,N,N)
{
    __shared__ ulonglong2 sW[8][NH];            // [j][h] = {(ws,ws),(wc,wc)}
    __shared__ unsigned long long sBb[NH];      // (b,b)

    const int tid = threadIdx.x;
    if (tid < 8 * NH) {
        int j = tid >> 3, h = tid & 7;
        float ws = pw[h * 16 + 2 * j + 0];
        float wc = pw[h * 16 + 2 * j + 1];
        ulonglong2 v; v.x = pack2(ws, ws); v.y = pack2(wc, wc);
        sW[j][h] = v;
    }
    if (tid < NH) sBb[tid] = pack2(pb[tid], pb[tid]);
    __syncthreads();

    const int b = blockIdx.y;
    const int r4 = (blockIdx.x * 256 + tid) * 4;
    if (r4 >= NN2) return;   // NN2 % 4 == 0

    const float4 xv = *reinterpret_cast<const float4*>(g_x + (size_t)b * NN2 + r4);

    unsigned long long acc[NH][2];
    #pragma unroll
    for (int h = 0; h < NH; h++) {
        unsigned long long bb = sBb[h];
        acc[h][0] = bb;
        acc[h][1] = bb;
    }

    // 100 / 10000^(j/8)
    const float SCJ[8] = {100.f, 31.622776601683793f, 10.f, 3.1622776601683795f,
                          1.f, 0.31622776601683794f, 0.1f, 0.031622776601683794f};

    #pragma unroll
    for (int j = 0; j < 8; j++) {
        float t0 = xv.x * SCJ[j];
        float t1 = xv.y * SCJ[j];
        float t2 = xv.z * SCJ[j];
        float t3 = xv.w * SCJ[j];
        unsigned long long fs0 = pack2(fast_sin(t0), fast_sin(t1));
        unsigned long long fs1 = pack2(fast_sin(t2), fast_sin(t3));
        unsigned long long fc0 = pack2(fast_cos(t0), fast_cos(t1));
        unsigned long long fc1 = pack2(fast_cos(t2), fast_cos(t3));
        #pragma unroll
        for (int h = 0; h < NH; h++) {
            ulonglong2 wv = sW[j][h];       // one LDS.128
            acc[h][0] = fma2(fs0, wv.x, acc[h][0]);
            acc[h][1] = fma2(fs1, wv.x, acc[h][1]);
            acc[h][0] = fma2(fc0, wv.y, acc[h][0]);
            acc[h][1] = fma2(fc1, wv.y, acc[h][1]);
        }
    }

    float* ob = out + ((size_t)b * NH) * NN2 + r4;
    #pragma unroll
    for (int h = 0; h < NH; h++) {
        float2 o0 = unpack2(acc[h][0]);
        float2 o1 = unpack2(acc[h][1]);
        float4 v = make_float4(fmaxf(o0.x, 0.f), fmaxf(o0.y, 0.f),
                               fmaxf(o1.x, 0.f), fmaxf(o1.y, 0.f));
        *reinterpret_cast<float4*>(ob + (size_t)h * NN2) = v;
    }
}

extern "C" void kernel_launch(void* const* d_in, const int* in_sizes, int n_in,
                              void* d_out, int out_size) {
    const float* queries = (const float*)d_in[0];
    const float* cur_ref = (const float*)d_in[1];
    // d_in[2] = prev_ref_points — unused by the reference
    const float* vote_w  = (const float*)d_in[3];
    const float* vote_b  = (const float*)d_in[4];
    const float* proj_w  = (const float*)d_in[5];
    const float* proj_b  = (const float*)d_in[6];
    float* out = (float*)d_out;

    hough_row2_kernel<<<NB * NN / 2, 256>>>(queries, cur_ref, vote_w, vote_b);

    dim3 gridB((NN2 / 4 + 255) / 256, NB);
    embed_proj_kernel<<<gridB, 256>>>(proj_w, proj_b, out);
}

// round 11
// speedup vs baseline: 1.0375x; 1.0375x over previous
#include <cuda_runtime.h>

#define NB 4
#define NN 900
#define ND 256
#define NV 16
#define NH 8
#define NN2 (NN * NN)

// scratch: x = 1 - imap/Z, laid out (B,N,N) contiguous
__device__ float g_x[NB * NN2];

__device__ __forceinline__ float fast_ex2(float x) {
    float r; asm("ex2.approx.ftz.f32 %0, %1;" : "=f"(r) : "f"(x)); return r;
}
__device__ __forceinline__ float fast_sin(float x) {
    float r; asm("sin.approx.ftz.f32 %0, %1;" : "=f"(r) : "f"(x)); return r;
}
__device__ __forceinline__ float fast_cos(float x) {
    float r; asm("cos.approx.ftz.f32 %0, %1;" : "=f"(r) : "f"(x)); return r;
}
__device__ __forceinline__ unsigned long long pack2(float a, float b) {
    unsigned long long r;
    asm("mov.b64 %0, {%1, %2};" : "=l"(r)
        : "r"(__float_as_uint(a)), "r"(__float_as_uint(b)));
    return r;
}
__device__ __forceinline__ float2 unpack2(unsigned long long v) {
    unsigned int lo, hi;
    asm("mov.b64 {%0, %1}, %2;" : "=r"(lo), "=r"(hi) : "l"(v));
    return make_float2(__uint_as_float(lo), __uint_as_float(hi));
}
__device__ __forceinline__ unsigned long long fma2(unsigned long long a,
                                                   unsigned long long b,
                                                   unsigned long long c) {
    unsigned long long d;
    asm("fma.rn.f32x2 %0, %1, %2, %3;" : "=l"(d) : "l"(a), "l"(b), "l"(c));
    return d;
}

// ---------------------------------------------------------------------------
// Kernel A: TWO rows (n0, n0+1) per block; 4 vote-groups of 64 threads.
// Inner loop: votes packed in f32x2 pairs -> 3 FFMA2 per (row, vote-pair).
// m-loop unrolled x4 for cross-iteration ILP.
// ---------------------------------------------------------------------------
__global__ __launch_bounds__(256, 4)
void hough_row2_kernel(const float* __restrict__ q,     // (B,N,D)
                       const float* __restrict__ cur,   // (B,N,4)
                       const float* __restrict__ vw,    // (32,D)
                       const float* __restrict__ vb)    // (32)
{
    const int pair = blockIdx.x;          // 0 .. NB*NN/2-1
    const int b    = pair / (NN / 2);
    const int n0   = (pair % (NN / 2)) * 2;
    const int bn0  = b * NN + n0;
    const int tid  = threadIdx.x;
    const int lane = tid & 31;
    const int w    = tid >> 5;
    const int g    = tid >> 6;            // vote group 0..3
    const int tg   = tid & 63;

    __shared__ float4 sq4[2][ND / 4];
    __shared__ float2 sC[NN];
    __shared__ float  sI[2][4][NN];
    __shared__ float4 sCoef[2][NV];       // (Ax, Ay, Ni, C0)
    __shared__ float  sVotes[2][2 * NV];
    __shared__ float  sRed[2][8];
    __shared__ float  sInvZ[2];

    if (tid < 128) {
        int r = tid >> 6, i = tid & 63;
        sq4[r][i] = *reinterpret_cast<const float4*>(q + (bn0 + r) * ND + i * 4);
    }
    for (int j = tid; j < NN; j += 256) {
        float4 c4 = *reinterpret_cast<const float4*>(cur + (b * NN + j) * 4);
        sC[j] = make_float2(c4.x, c4.y);
    }
    __syncthreads();

    // votes for BOTH rows: weight vectors loaded once, used with both q rows
    {
        const int k0 = w * 4;
        const float4* w0 = reinterpret_cast<const float4*>(vw + (k0 + 0) * ND);
        const float4* w1 = reinterpret_cast<const float4*>(vw + (k0 + 1) * ND);
        const float4* w2 = reinterpret_cast<const float4*>(vw + (k0 + 2) * ND);
        const float4* w3 = reinterpret_cast<const float4*>(vw + (k0 + 3) * ND);
        float a0 = 0.f, a1 = 0.f, a2 = 0.f, a3 = 0.f;
        float b0 = 0.f, b1 = 0.f, b2 = 0.f, b3 = 0.f;
        #pragma unroll
        for (int i = 0; i < 2; i++) {
            int d = lane + 32 * i;
            float4 qa = sq4[0][d];
            float4 qb = sq4[1][d];
            float4 v0 = __ldg(w0 + d);
            float4 v1 = __ldg(w1 + d);
            float4 v2 = __ldg(w2 + d);
            float4 v3 = __ldg(w3 + d);
            a0 = fmaf(qa.x, v0.x, fmaf(qa.y, v0.y, fmaf(qa.z, v0.z, fmaf(qa.w, v0.w, a0))));
            a1 = fmaf(qa.x, v1.x, fmaf(qa.y, v1.y, fmaf(qa.z, v1.z, fmaf(qa.w, v1.w, a1))));
            a2 = fmaf(qa.x, v2.x, fmaf(qa.y, v2.y, fmaf(qa.z, v2.z, fmaf(qa.w, v2.w, a2))));
            a3 = fmaf(qa.x, v3.x, fmaf(qa.y, v3.y, fmaf(qa.z, v3.z, fmaf(qa.w, v3.w, a3))));
            b0 = fmaf(qb.x, v0.x, fmaf(qb.y, v0.y, fmaf(qb.z, v0.z, fmaf(qb.w, v0.w, b0))));
            b1 = fmaf(qb.x, v1.x, fmaf(qb.y, v1.y, fmaf(qb.z, v1.z, fmaf(qb.w, v1.w, b1))));
            b2 = fmaf(qb.x, v2.x, fmaf(qb.y, v2.y, fmaf(qb.z, v2.z, fmaf(qb.w, v2.w, b2))));
            b3 = fmaf(qb.x, v3.x, fmaf(qb.y, v3.y, fmaf(qb.z, v3.z, fmaf(qb.w, v3.w, b3))));
        }
        #pragma unroll
        for (int o = 16; o; o >>= 1) {
            a0 += __shfl_down_sync(0xffffffffu, a0, o);
            a1 += __shfl_down_sync(0xffffffffu, a1, o);
            a2 += __shfl_down_sync(0xffffffffu, a2, o);
            a3 += __shfl_down_sync(0xffffffffu, a3, o);
            b0 += __shfl_down_sync(0xffffffffu, b0, o);
            b1 += __shfl_down_sync(0xffffffffu, b1, o);
            b2 += __shfl_down_sync(0xffffffffu, b2, o);
            b3 += __shfl_down_sync(0xffffffffu, b3, o);
        }
        if (lane == 0) {
            sVotes[0][k0 + 0] = a0 + vb[k0 + 0];
            sVotes[0][k0 + 1] = a1 + vb[k0 + 1];
            sVotes[0][k0 + 2] = a2 + vb[k0 + 2];
            sVotes[0][k0 + 3] = a3 + vb[k0 + 3];
            sVotes[1][k0 + 0] = b0 + vb[k0 + 0];
            sVotes[1][k0 + 1] = b1 + vb[k0 + 1];
            sVotes[1][k0 + 2] = b2 + vb[k0 + 2];
            sVotes[1][k0 + 3] = b3 + vb[k0 + 3];
        }
    }
    __syncthreads();

    if (tid < 2 * NV) {
        int r = tid >> 4, v = tid & 15;
        int n = n0 + r, bn = bn0 + r;
        float cx = cur[bn * 4 + 0];
        float cy = cur[bn * 4 + 1];
        float vx = cx + sVotes[r][2 * v + 0];
        float vy = cy + sVotes[r][2 * v + 1];
        // reference quirk: sigma index is (n*V + v) mod N
        int idx  = (n * NV + v) % NN;
        float c2 = cur[(b * NN + idx) * 4 + 2];
        float c3 = cur[(b * NN + idx) * 4 + 3];
        float s  = c2 + c3;   // 4*sigma
        float ninv = -11.541560327111707f / (s * s);   // -8*log2e / s^2
        float vv   = fmaf(vx, vx, vy * vy);
        sCoef[r][v] = make_float4(-2.f * ninv * vx, -2.f * ninv * vy,
                                  ninv, ninv * vv);
    }
    __syncthreads();

    // registerize this group's 4 votes for both rows as f32x2 vote-pairs
    unsigned long long Axp[2][2], Ayp[2][2], Nip[2][2], C0p[2][2];
    #pragma unroll
    for (int r = 0; r < 2; r++)
        #pragma unroll
        for (int p = 0; p < 2; p++) {
            float4 ca = sCoef[r][g * 4 + 2 * p + 0];
            float4 cb = sCoef[r][g * 4 + 2 * p + 1];
            Axp[r][p] = pack2(ca.x, cb.x);
            Ayp[r][p] = pack2(ca.y, cb.y);
            Nip[r][p] = pack2(ca.z, cb.z);
            C0p[r][p] = pack2(ca.w, cb.w);
        }

    float part0 = 0.f, part1 = 0.f;
    #pragma unroll 4
    for (int m = tg; m < NN; m += 64) {
        float2 c  = sC[m];
        float  cc = fmaf(c.x, c.x, c.y * c.y);
        unsigned long long cxd = pack2(c.x, c.x);
        unsigned long long cyd = pack2(c.y, c.y);
        unsigned long long ccd = pack2(cc, cc);

        unsigned long long e00 = fma2(cxd, Axp[0][0], fma2(cyd, Ayp[0][0], fma2(ccd, Nip[0][0], C0p[0][0])));
        unsigned long long e01 = fma2(cxd, Axp[0][1], fma2(cyd, Ayp[0][1], fma2(ccd, Nip[0][1], C0p[0][1])));
        unsigned long long e10 = fma2(cxd, Axp[1][0], fma2(cyd, Ayp[1][0], fma2(ccd, Nip[1][0], C0p[1][0])));
        unsigned long long e11 = fma2(cxd, Axp[1][1], fma2(cyd, Ayp[1][1], fma2(ccd, Nip[1][1], C0p[1][1])));

        float2 f00 = unpack2(e00);
        float2 f01 = unpack2(e01);
        float2 f10 = unpack2(e10);
        float2 f11 = unpack2(e11);

        float acc0 = (fast_ex2(fminf(f00.x, 0.f)) + fast_ex2(fminf(f00.y, 0.f)))
                   + (fast_ex2(fminf(f01.x, 0.f)) + fast_ex2(fminf(f01.y, 0.f)));
        float acc1 = (fast_ex2(fminf(f10.x, 0.f)) + fast_ex2(fminf(f10.y, 0.f)))
                   + (fast_ex2(fminf(f11.x, 0.f)) + fast_ex2(fminf(f11.y, 0.f)));

        sI[0][g][m] = acc0;
        sI[1][g][m] = acc1;
        part0 += acc0;
        part1 += acc1;
    }
    #pragma unroll
    for (int o = 16; o; o >>= 1) {
        part0 += __shfl_down_sync(0xffffffffu, part0, o);
        part1 += __shfl_down_sync(0xffffffffu, part1, o);
    }
    if (lane == 0) { sRed[0][w] = part0; sRed[1][w] = part1; }
    __syncthreads();
    if (tid < 2) {
        float t = 0.f;
        #pragma unroll
        for (int i = 0; i < 8; i++) t += sRed[tid][i];
        sInvZ[tid] = 1.f / fmaxf(t, 1e-12f);
    }
    __syncthreads();
    const float invZ0 = sInvZ[0];
    const float invZ1 = sInvZ[1];

    float* xr0 = g_x + (size_t)bn0 * NN;
    for (int m = tid; m < NN; m += 256) {
        float s0 = (sI[0][0][m] + sI[0][1][m]) + (sI[0][2][m] + sI[0][3][m]);
        float s1 = (sI[1][0][m] + sI[1][1][m]) + (sI[1][2][m] + sI[1][3][m]);
        xr0[m]      = 1.f - s0 * invZ0;
        xr0[NN + m] = 1.f - s1 * invZ1;
    }
}

// ---------------------------------------------------------------------------
// Kernel B: 4 elements/thread, HEAD-PAIR f32x2 packing: each accumulator
// lane-pair is (head 2p, head 2p+1) for one element. Weights load directly
// as packed pairs (LDS.128, no dup movs); only features need (s,s) dup.
// Outputs transposed back to per-head float4 stores via register unpacks.
// ---------------------------------------------------------------------------
__global__ __launch_bounds__(256, 3)
void embed_proj_kernel(const float* __restrict__ pw,   // (H,16)
                       const float* __restrict__ pb,   // (H)
                       float* __restrict__ out)        // (B,H,N,N)
{
    __shared__ ulonglong2 sW[8][NH / 2];        // [j][hp] = {(ws_h0,ws_h1),(wc_h0,wc_h1)}
    __shared__ unsigned long long sBp[NH / 2];  // (b_h0, b_h1)

    const int tid = threadIdx.x;
    if (tid < 8 * (NH / 2)) {
        int j = tid >> 2, hp = tid & 3;
        int h0 = 2 * hp, h1 = 2 * hp + 1;
        ulonglong2 v;
        v.x = pack2(pw[h0 * 16 + 2 * j + 0], pw[h1 * 16 + 2 * j + 0]);
        v.y = pack2(pw[h0 * 16 + 2 * j + 1], pw[h1 * 16 + 2 * j + 1]);
        sW[j][hp] = v;
    }
    if (tid < NH / 2) sBp[tid] = pack2(pb[2 * tid], pb[2 * tid + 1]);
    __syncthreads();

    const int b = blockIdx.y;
    const int r4 = (blockIdx.x * 256 + tid) * 4;
    if (r4 >= NN2) return;   // NN2 % 4 == 0

    const float4 xv = *reinterpret_cast<const float4*>(g_x + (size_t)b * NN2 + r4);
    const float xs[4] = {xv.x, xv.y, xv.z, xv.w};

    unsigned long long acc[NH / 2][4];   // [head-pair][element]
    #pragma unroll
    for (int hp = 0; hp < NH / 2; hp++) {
        unsigned long long bb = sBp[hp];
        #pragma unroll
        for (int e = 0; e < 4; e++) acc[hp][e] = bb;
    }

    // 100 / 10000^(j/8)
    const float SCJ[8] = {100.f, 31.622776601683793f, 10.f, 3.1622776601683795f,
                          1.f, 0.31622776601683794f, 0.1f, 0.031622776601683794f};

    #pragma unroll
    for (int j = 0; j < 8; j++) {
        unsigned long long sd[4], cd[4];
        #pragma unroll
        for (int e = 0; e < 4; e++) {
            float t = xs[e] * SCJ[j];
            float s = fast_sin(t);
            float c = fast_cos(t);
            sd[e] = pack2(s, s);   // 1 dup MOV each
            cd[e] = pack2(c, c);
        }
        #pragma unroll
        for (int hp = 0; hp < NH / 2; hp++) {
            ulonglong2 wv = sW[j][hp];    // LDS.128, directly usable
            #pragma unroll
            for (int e = 0; e < 4; e++) {
                acc[hp][e] = fma2(sd[e], wv.x, acc[hp][e]);
                acc[hp][e] = fma2(cd[e], wv.y, acc[hp][e]);
            }
        }
    }

    float* ob = out + ((size_t)b * NH) * NN2 + r4;
    #pragma unroll
    for (int hp = 0; hp < NH / 2; hp++) {
        float2 a0 = unpack2(acc[hp][0]);
        float2 a1 = unpack2(acc[hp][1]);
        float2 a2 = unpack2(acc[hp][2]);
        float2 a3 = unpack2(acc[hp][3]);
        float4 v0 = make_float4(fmaxf(a0.x, 0.f), fmaxf(a1.x, 0.f),
                                fmaxf(a2.x, 0.f), fmaxf(a3.x, 0.f));
        float4 v1 = make_float4(fmaxf(a0.y, 0.f), fmaxf(a1.y, 0.f),
                                fmaxf(a2.y, 0.f), fmaxf(a3.y, 0.f));
        *reinterpret_cast<float4*>(ob + (size_t)(2 * hp + 0) * NN2) = v0;
        *reinterpret_cast<float4*>(ob + (size_t)(2 * hp + 1) * NN2) = v1;
    }
}

extern "C" void kernel_launch(void* const* d_in, const int* in_sizes, int n_in,
                              void* d_out, int out_size) {
    const float* queries = (const float*)d_in[0];
    const float* cur_ref = (const float*)d_in[1];
    // d_in[2] = prev_ref_points — unused by the reference
    const float* vote_w  = (const float*)d_in[3];
    const float* vote_b  = (const float*)d_in[4];
    const float* proj_w  = (const float*)d_in[5];
    const float* proj_b  = (const float*)d_in[6];
    float* out = (float*)d_out;

    hough_row2_kernel<<<NB * NN / 2, 256>>>(queries, cur_ref, vote_w, vote_b);

    dim3 gridB((NN2 / 4 + 255) / 256, NB);
    embed_proj_kernel<<<gridB, 256>>>(proj_w, proj_b, out);
}

// round 12
// speedup vs baseline: 1.0430x; 1.0054x over previous
#include <cuda_runtime.h>

#define NB 4
#define NN 900
#define ND 256
#define NV 16
#define NH 8
#define NN2 (NN * NN)

// scratch: x = 1 - imap/Z, laid out (B,N,N) contiguous
__device__ float g_x[NB * NN2];

__device__ __forceinline__ float fast_ex2(float x) {
    float r; asm("ex2.approx.ftz.f32 %0, %1;" : "=f"(r) : "f"(x)); return r;
}
__device__ __forceinline__ float fast_sin(float x) {
    float r; asm("sin.approx.ftz.f32 %0, %1;" : "=f"(r) : "f"(x)); return r;
}
__device__ __forceinline__ float fast_cos(float x) {
    float r; asm("cos.approx.ftz.f32 %0, %1;" : "=f"(r) : "f"(x)); return r;
}
__device__ __forceinline__ unsigned long long pack2(float a, float b) {
    unsigned long long r;
    asm("mov.b64 %0, {%1, %2};" : "=l"(r)
        : "r"(__float_as_uint(a)), "r"(__float_as_uint(b)));
    return r;
}
__device__ __forceinline__ float2 unpack2(unsigned long long v) {
    unsigned int lo, hi;
    asm("mov.b64 {%0, %1}, %2;" : "=r"(lo), "=r"(hi) : "l"(v));
    return make_float2(__uint_as_float(lo), __uint_as_float(hi));
}
__device__ __forceinline__ unsigned long long fma2(unsigned long long a,
                                                   unsigned long long b,
                                                   unsigned long long c) {
    unsigned long long d;
    asm("fma.rn.f32x2 %0, %1, %2, %3;" : "=l"(d) : "l"(a), "l"(b), "l"(c));
    return d;
}

// ---------------------------------------------------------------------------
// Kernel A: TWO rows (n0, n0+1) per block; 4 vote-groups of 64 threads.
// Inner loop: votes packed in f32x2 pairs -> 3 FFMA2 per (row, vote-pair).
// m-loop unrolled x2 (x4 regressed: register pressure).
// ---------------------------------------------------------------------------
__global__ __launch_bounds__(256, 4)
void hough_row2_kernel(const float* __restrict__ q,     // (B,N,D)
                       const float* __restrict__ cur,   // (B,N,4)
                       const float* __restrict__ vw,    // (32,D)
                       const float* __restrict__ vb)    // (32)
{
    const int pair = blockIdx.x;          // 0 .. NB*NN/2-1
    const int b    = pair / (NN / 2);
    const int n0   = (pair % (NN / 2)) * 2;
    const int bn0  = b * NN + n0;
    const int tid  = threadIdx.x;
    const int lane = tid & 31;
    const int w    = tid >> 5;
    const int g    = tid >> 6;            // vote group 0..3
    const int tg   = tid & 63;

    __shared__ float4 sq4[2][ND / 4];
    __shared__ float2 sC[NN];
    __shared__ float  sI[2][4][NN];
    __shared__ float4 sCoef[2][NV];       // (Ax, Ay, Ni, C0)
    __shared__ float  sVotes[2][2 * NV];
    __shared__ float  sRed[2][8];
    __shared__ float  sInvZ[2];

    if (tid < 128) {
        int r = tid >> 6, i = tid & 63;
        sq4[r][i] = *reinterpret_cast<const float4*>(q + (bn0 + r) * ND + i * 4);
    }
    for (int j = tid; j < NN; j += 256) {
        float4 c4 = *reinterpret_cast<const float4*>(cur + (b * NN + j) * 4);
        sC[j] = make_float2(c4.x, c4.y);
    }
    __syncthreads();

    // votes for BOTH rows: weight vectors loaded once, used with both q rows
    {
        const int k0 = w * 4;
        const float4* w0 = reinterpret_cast<const float4*>(vw + (k0 + 0) * ND);
        const float4* w1 = reinterpret_cast<const float4*>(vw + (k0 + 1) * ND);
        const float4* w2 = reinterpret_cast<const float4*>(vw + (k0 + 2) * ND);
        const float4* w3 = reinterpret_cast<const float4*>(vw + (k0 + 3) * ND);
        float a0 = 0.f, a1 = 0.f, a2 = 0.f, a3 = 0.f;
        float b0 = 0.f, b1 = 0.f, b2 = 0.f, b3 = 0.f;
        #pragma unroll
        for (int i = 0; i < 2; i++) {
            int d = lane + 32 * i;
            float4 qa = sq4[0][d];
            float4 qb = sq4[1][d];
            float4 v0 = __ldg(w0 + d);
            float4 v1 = __ldg(w1 + d);
            float4 v2 = __ldg(w2 + d);
            float4 v3 = __ldg(w3 + d);
            a0 = fmaf(qa.x, v0.x, fmaf(qa.y, v0.y, fmaf(qa.z, v0.z, fmaf(qa.w, v0.w, a0))));
            a1 = fmaf(qa.x, v1.x, fmaf(qa.y, v1.y, fmaf(qa.z, v1.z, fmaf(qa.w, v1.w, a1))));
            a2 = fmaf(qa.x, v2.x, fmaf(qa.y, v2.y, fmaf(qa.z, v2.z, fmaf(qa.w, v2.w, a2))));
            a3 = fmaf(qa.x, v3.x, fmaf(qa.y, v3.y, fmaf(qa.z, v3.z, fmaf(qa.w, v3.w, a3))));
            b0 = fmaf(qb.x, v0.x, fmaf(qb.y, v0.y, fmaf(qb.z, v0.z, fmaf(qb.w, v0.w, b0))));
            b1 = fmaf(qb.x, v1.x, fmaf(qb.y, v1.y, fmaf(qb.z, v1.z, fmaf(qb.w, v1.w, b1))));
            b2 = fmaf(qb.x, v2.x, fmaf(qb.y, v2.y, fmaf(qb.z, v2.z, fmaf(qb.w, v2.w, b2))));
            b3 = fmaf(qb.x, v3.x, fmaf(qb.y, v3.y, fmaf(qb.z, v3.z, fmaf(qb.w, v3.w, b3))));
        }
        #pragma unroll
        for (int o = 16; o; o >>= 1) {
            a0 += __shfl_down_sync(0xffffffffu, a0, o);
            a1 += __shfl_down_sync(0xffffffffu, a1, o);
            a2 += __shfl_down_sync(0xffffffffu, a2, o);
            a3 += __shfl_down_sync(0xffffffffu, a3, o);
            b0 += __shfl_down_sync(0xffffffffu, b0, o);
            b1 += __shfl_down_sync(0xffffffffu, b1, o);
            b2 += __shfl_down_sync(0xffffffffu, b2, o);
            b3 += __shfl_down_sync(0xffffffffu, b3, o);
        }
        if (lane == 0) {
            sVotes[0][k0 + 0] = a0 + vb[k0 + 0];
            sVotes[0][k0 + 1] = a1 + vb[k0 + 1];
            sVotes[0][k0 + 2] = a2 + vb[k0 + 2];
            sVotes[0][k0 + 3] = a3 + vb[k0 + 3];
            sVotes[1][k0 + 0] = b0 + vb[k0 + 0];
            sVotes[1][k0 + 1] = b1 + vb[k0 + 1];
            sVotes[1][k0 + 2] = b2 + vb[k0 + 2];
            sVotes[1][k0 + 3] = b3 + vb[k0 + 3];
        }
    }
    __syncthreads();

    if (tid < 2 * NV) {
        int r = tid >> 4, v = tid & 15;
        int n = n0 + r, bn = bn0 + r;
        float cx = cur[bn * 4 + 0];
        float cy = cur[bn * 4 + 1];
        float vx = cx + sVotes[r][2 * v + 0];
        float vy = cy + sVotes[r][2 * v + 1];
        // reference quirk: sigma index is (n*V + v) mod N
        int idx  = (n * NV + v) % NN;
        float c2 = cur[(b * NN + idx) * 4 + 2];
        float c3 = cur[(b * NN + idx) * 4 + 3];
        float s  = c2 + c3;   // 4*sigma
        float ninv = -11.541560327111707f / (s * s);   // -8*log2e / s^2
        float vv   = fmaf(vx, vx, vy * vy);
        sCoef[r][v] = make_float4(-2.f * ninv * vx, -2.f * ninv * vy,
                                  ninv, ninv * vv);
    }
    __syncthreads();

    // registerize this group's 4 votes for both rows as f32x2 vote-pairs
    unsigned long long Axp[2][2], Ayp[2][2], Nip[2][2], C0p[2][2];
    #pragma unroll
    for (int r = 0; r < 2; r++)
        #pragma unroll
        for (int p = 0; p < 2; p++) {
            float4 ca = sCoef[r][g * 4 + 2 * p + 0];
            float4 cb = sCoef[r][g * 4 + 2 * p + 1];
            Axp[r][p] = pack2(ca.x, cb.x);
            Ayp[r][p] = pack2(ca.y, cb.y);
            Nip[r][p] = pack2(ca.z, cb.z);
            C0p[r][p] = pack2(ca.w, cb.w);
        }

    float part0 = 0.f, part1 = 0.f;
    #pragma unroll 2
    for (int m = tg; m < NN; m += 64) {
        float2 c  = sC[m];
        float  cc = fmaf(c.x, c.x, c.y * c.y);
        unsigned long long cxd = pack2(c.x, c.x);
        unsigned long long cyd = pack2(c.y, c.y);
        unsigned long long ccd = pack2(cc, cc);

        unsigned long long e00 = fma2(cxd, Axp[0][0], fma2(cyd, Ayp[0][0], fma2(ccd, Nip[0][0], C0p[0][0])));
        unsigned long long e01 = fma2(cxd, Axp[0][1], fma2(cyd, Ayp[0][1], fma2(ccd, Nip[0][1], C0p[0][1])));
        unsigned long long e10 = fma2(cxd, Axp[1][0], fma2(cyd, Ayp[1][0], fma2(ccd, Nip[1][0], C0p[1][0])));
        unsigned long long e11 = fma2(cxd, Axp[1][1], fma2(cyd, Ayp[1][1], fma2(ccd, Nip[1][1], C0p[1][1])));

        float2 f00 = unpack2(e00);
        float2 f01 = unpack2(e01);
        float2 f10 = unpack2(e10);
        float2 f11 = unpack2(e11);

        float acc0 = (fast_ex2(fminf(f00.x, 0.f)) + fast_ex2(fminf(f00.y, 0.f)))
                   + (fast_ex2(fminf(f01.x, 0.f)) + fast_ex2(fminf(f01.y, 0.f)));
        float acc1 = (fast_ex2(fminf(f10.x, 0.f)) + fast_ex2(fminf(f10.y, 0.f)))
                   + (fast_ex2(fminf(f11.x, 0.f)) + fast_ex2(fminf(f11.y, 0.f)));

        sI[0][g][m] = acc0;
        sI[1][g][m] = acc1;
        part0 += acc0;
        part1 += acc1;
    }
    #pragma unroll
    for (int o = 16; o; o >>= 1) {
        part0 += __shfl_down_sync(0xffffffffu, part0, o);
        part1 += __shfl_down_sync(0xffffffffu, part1, o);
    }
    if (lane == 0) { sRed[0][w] = part0; sRed[1][w] = part1; }
    __syncthreads();
    if (tid < 2) {
        float t = 0.f;
        #pragma unroll
        for (int i = 0; i < 8; i++) t += sRed[tid][i];
        sInvZ[tid] = 1.f / fmaxf(t, 1e-12f);
    }
    __syncthreads();
    const float invZ0 = sInvZ[0];
    const float invZ1 = sInvZ[1];

    float* xr0 = g_x + (size_t)bn0 * NN;
    for (int m = tid; m < NN; m += 256) {
        float s0 = (sI[0][0][m] + sI[0][1][m]) + (sI[0][2][m] + sI[0][3][m]);
        float s1 = (sI[1][0][m] + sI[1][1][m]) + (sI[1][2][m] + sI[1][3][m]);
        xr0[m]      = 1.f - s0 * invZ0;
        xr0[NN + m] = 1.f - s1 * invZ1;
    }
}

// ---------------------------------------------------------------------------
// Kernel B: 2 elements/thread, HEAD-PAIR f32x2 packing (acc lanes = heads).
// Small register footprint (8 u64 accs) -> 5 CTAs/SM for issue bandwidth.
// Weights load directly as packed head-pairs (LDS.128, no dup movs).
// ---------------------------------------------------------------------------
__global__ __launch_bounds__(256, 5)
void embed_proj_kernel(const float* __restrict__ pw,   // (H,16)
                       const float* __restrict__ pb,   // (H)
                       float* __restrict__ out)        // (B,H,N,N)
{
    __shared__ ulonglong2 sW[8][NH / 2];        // [j][hp] = {(ws_h0,ws_h1),(wc_h0,wc_h1)}
    __shared__ unsigned long long sBp[NH / 2];  // (b_h0, b_h1)

    const int tid = threadIdx.x;
    if (tid < 8 * (NH / 2)) {
        int j = tid >> 2, hp = tid & 3;
        int h0 = 2 * hp, h1 = 2 * hp + 1;
        ulonglong2 v;
        v.x = pack2(pw[h0 * 16 + 2 * j + 0], pw[h1 * 16 + 2 * j + 0]);
        v.y = pack2(pw[h0 * 16 + 2 * j + 1], pw[h1 * 16 + 2 * j + 1]);
        sW[j][hp] = v;
    }
    if (tid < NH / 2) sBp[tid] = pack2(pb[2 * tid], pb[2 * tid + 1]);
    __syncthreads();

    const int b = blockIdx.y;
    const int r2 = (blockIdx.x * 256 + tid) * 2;
    if (r2 >= NN2) return;   // NN2 % 2 == 0

    const float2 xv = *reinterpret_cast<const float2*>(g_x + (size_t)b * NN2 + r2);

    unsigned long long acc[NH / 2][2];   // [head-pair][element]
    #pragma unroll
    for (int hp = 0; hp < NH / 2; hp++) {
        unsigned long long bb = sBp[hp];
        acc[hp][0] = bb;
        acc[hp][1] = bb;
    }

    // 100 / 10000^(j/8)
    const float SCJ[8] = {100.f, 31.622776601683793f, 10.f, 3.1622776601683795f,
                          1.f, 0.31622776601683794f, 0.1f, 0.031622776601683794f};

    #pragma unroll
    for (int j = 0; j < 8; j++) {
        float t0 = xv.x * SCJ[j];
        float t1 = xv.y * SCJ[j];
        float s0 = fast_sin(t0), c0 = fast_cos(t0);
        float s1 = fast_sin(t1), c1 = fast_cos(t1);
        unsigned long long sd0 = pack2(s0, s0);
        unsigned long long cd0 = pack2(c0, c0);
        unsigned long long sd1 = pack2(s1, s1);
        unsigned long long cd1 = pack2(c1, c1);
        #pragma unroll
        for (int hp = 0; hp < NH / 2; hp++) {
            ulonglong2 wv = sW[j][hp];    // LDS.128
            acc[hp][0] = fma2(sd0, wv.x, acc[hp][0]);
            acc[hp][1] = fma2(sd1, wv.x, acc[hp][1]);
            acc[hp][0] = fma2(cd0, wv.y, acc[hp][0]);
            acc[hp][1] = fma2(cd1, wv.y, acc[hp][1]);
        }
    }

    float* ob = out + ((size_t)b * NH) * NN2 + r2;
    #pragma unroll
    for (int hp = 0; hp < NH / 2; hp++) {
        float2 a0 = unpack2(acc[hp][0]);   // (h0, h1) for element 0
        float2 a1 = unpack2(acc[hp][1]);   // (h0, h1) for element 1
        *reinterpret_cast<float2*>(ob + (size_t)(2 * hp + 0) * NN2) =
            make_float2(fmaxf(a0.x, 0.f), fmaxf(a1.x, 0.f));
        *reinterpret_cast<float2*>(ob + (size_t)(2 * hp + 1) * NN2) =
            make_float2(fmaxf(a0.y, 0.f), fmaxf(a1.y, 0.f));
    }
}

extern "C" void kernel_launch(void* const* d_in, const int* in_sizes, int n_in,
                              void* d_out, int out_size) {
    const float* queries = (const float*)d_in[0];
    const float* cur_ref = (const float*)d_in[1];
    // d_in[2] = prev_ref_points — unused by the reference
    const float* vote_w  = (const float*)d_in[3];
    const float* vote_b  = (const float*)d_in[4];
    const float* proj_w  = (const float*)d_in[5];
    const float* proj_b  = (const float*)d_in[6];
    float* out = (float*)d_out;

    hough_row2_kernel<<<NB * NN / 2, 256>>>(queries, cur_ref, vote_w, vote_b);

    dim3 gridB((NN2 / 2 + 255) / 256, NB);
    embed_proj_kernel<<<gridB, 256>>>(proj_w, proj_b, out);
}